// round 1
// baseline (speedup 1.0000x reference)
#include <cuda_runtime.h>

#define NBINS 4096   // 16^3

__device__ unsigned int g_hist_src[NBINS];

__global__ void zero_hist_kernel() {
    int i = blockIdx.x * blockDim.x + threadIdx.x;
    if (i < NBINS) g_hist_src[i] = 0u;
}

__device__ __forceinline__ int qbin(float c) {
    int q = (int)(c * 15.0f);      // truncation == jnp astype(int32) for c >= 0
    q = q < 0 ? 0 : q;
    return q > 15 ? 15 : q;
}

__device__ __forceinline__ int flat3(float r, float g, float b) {
    return (qbin(r) * 16 + qbin(g)) * 16 + qbin(b);
}

__global__ void __launch_bounds__(512) src_hist_kernel(
        const float4* __restrict__ srcv, const float* __restrict__ src,
        int nquads, int npix) {
    __shared__ unsigned int sh[NBINS];
    for (int i = threadIdx.x; i < NBINS; i += blockDim.x) sh[i] = 0u;
    __syncthreads();

    int tid = blockIdx.x * blockDim.x + threadIdx.x;
    int stride = gridDim.x * blockDim.x;

    // 4 pixels (12 floats = 3 float4) per thread per iteration; 48B is 16B-aligned.
    for (int q = tid; q < nquads; q += stride) {
        float4 a = srcv[3 * q + 0];
        float4 b = srcv[3 * q + 1];
        float4 c = srcv[3 * q + 2];
        atomicAdd(&sh[flat3(a.x, a.y, a.z)], 1u);
        atomicAdd(&sh[flat3(a.w, b.x, b.y)], 1u);
        atomicAdd(&sh[flat3(b.z, b.w, c.x)], 1u);
        atomicAdd(&sh[flat3(c.y, c.z, c.w)], 1u);
    }

    // tail pixels (none for N=8388608, kept for generality)
    int base = nquads * 4;
    for (int p = base + tid; p < npix; p += stride) {
        atomicAdd(&sh[flat3(src[3 * p], src[3 * p + 1], src[3 * p + 2])], 1u);
    }

    __syncthreads();
    for (int i = threadIdx.x; i < NBINS; i += blockDim.x) {
        unsigned v = sh[i];
        if (v) atomicAdd(&g_hist_src[i], v);
    }
}

// Single block: builds the (tiny) palette histogram in smem, then computes the loss.
__global__ void __launch_bounds__(512) loss_kernel(
        const float* __restrict__ pal, int M, int npix, float* __restrict__ out) {
    __shared__ unsigned int sh[NBINS];
    __shared__ float red[16];
    for (int i = threadIdx.x; i < NBINS; i += blockDim.x) sh[i] = 0u;
    __syncthreads();

    for (int p = threadIdx.x; p < M; p += blockDim.x) {
        atomicAdd(&sh[flat3(pal[3 * p], pal[3 * p + 1], pal[3 * p + 2])], 1u);
    }
    __syncthreads();

    // hist sums are exactly npix and M (every pixel lands in exactly one bin);
    // adding 1e-8 is a no-op in fp32 at these magnitudes, matching the reference.
    float invS = 1.0f / ((float)npix + 1e-8f);
    float invT = 1.0f / ((float)M + 1e-8f);

    float acc = 0.0f;
    for (int i = threadIdx.x; i < NBINS; i += blockDim.x) {
        acc += fabsf((float)g_hist_src[i] * invS - (float)sh[i] * invT);
    }

    // block reduction: warp shuffle then cross-warp
    for (int off = 16; off; off >>= 1) acc += __shfl_down_sync(0xffffffffu, acc, off);
    if ((threadIdx.x & 31) == 0) red[threadIdx.x >> 5] = acc;
    __syncthreads();
    if (threadIdx.x < 16) {
        float v = red[threadIdx.x];
        for (int off = 8; off; off >>= 1) v += __shfl_down_sync(0xffffu, v, off);
        if (threadIdx.x == 0) out[0] = v * (1.0f / (float)NBINS);
    }
}

extern "C" void kernel_launch(void* const* d_in, const int* in_sizes, int n_in,
                              void* d_out, int out_size) {
    const float* src = (const float*)d_in[0];   // (N, 3) float32
    const float* pal = (const float*)d_in[1];   // (M, 3) float32
    int N = in_sizes[0] / 3;
    int M = in_sizes[1] / 3;
    int nquads = N / 4;

    zero_hist_kernel<<<(NBINS + 255) / 256, 256>>>();
    src_hist_kernel<<<296, 512>>>((const float4*)src, src, nquads, N);
    loss_kernel<<<1, 512>>>(pal, M, N, (float*)d_out);
}

// round 2
// speedup vs baseline: 1.0091x; 1.0091x over previous
#include <cuda_runtime.h>

#define NBINS 4096            // 16^3
#define NPAIR (NBINS / 2)
#define BLOCKS 296
#define THREADS 1024

// Zero-initialized at module load; the kernel self-cleans both so every graph
// replay starts from the same state (deterministic, no separate zero kernel).
__device__ unsigned long long g_hist64[NPAIR];
__device__ unsigned int g_arrival;

__device__ __forceinline__ int qbin(float c) {
    int q = (int)(c * 15.0f);          // trunc == astype(int32) for c >= 0
    q = q < 0 ? 0 : q;
    return q > 15 ? 15 : q;
}

__device__ __forceinline__ int flat3(float r, float g, float b) {
    return (qbin(r) * 16 + qbin(g)) * 16 + qbin(b);
}

__global__ void __launch_bounds__(THREADS, 2) fused_hist_loss_kernel(
        const float4* __restrict__ srcv, const float* __restrict__ src,
        const float* __restrict__ pal,
        int nquads, int npix, int M, float* __restrict__ out) {
    __shared__ unsigned int sh[NBINS];
    __shared__ float red[THREADS / 32];
    __shared__ bool is_last;

    for (int i = threadIdx.x; i < NBINS; i += THREADS) sh[i] = 0u;
    __syncthreads();

    int tid = blockIdx.x * THREADS + threadIdx.x;
    const int stride = BLOCKS * THREADS;

    // 4 pixels (3 float4 = 48 B) per thread per iteration; streaming loads.
    for (int q = tid; q < nquads; q += stride) {
        float4 a = __ldcs(&srcv[3 * q + 0]);
        float4 b = __ldcs(&srcv[3 * q + 1]);
        float4 c = __ldcs(&srcv[3 * q + 2]);
        atomicAdd(&sh[flat3(a.x, a.y, a.z)], 1u);
        atomicAdd(&sh[flat3(a.w, b.x, b.y)], 1u);
        atomicAdd(&sh[flat3(b.z, b.w, c.x)], 1u);
        atomicAdd(&sh[flat3(c.y, c.z, c.w)], 1u);
    }
    // tail pixels (none for npix % 4 == 0; kept for generality)
    for (int p = nquads * 4 + tid; p < npix; p += stride) {
        atomicAdd(&sh[flat3(src[3 * p], src[3 * p + 1], src[3 * p + 2])], 1u);
    }
    __syncthreads();

    // Flush: pack two u32 bin counts into one u64 atomic (halves REDG count).
    for (int i = threadIdx.x; i < NPAIR; i += THREADS) {
        unsigned int lo = sh[2 * i], hi = sh[2 * i + 1];
        if (lo | hi)
            atomicAdd(&g_hist64[i],
                      (unsigned long long)lo | ((unsigned long long)hi << 32));
    }
    __threadfence();
    if (threadIdx.x == 0) {
        unsigned int t = atomicAdd(&g_arrival, 1u);
        is_last = (t == BLOCKS - 1);
    }
    __syncthreads();
    if (!is_last) return;

    // ---- last block only: palette histogram + L1 loss + self-clean ----
    for (int i = threadIdx.x; i < NBINS; i += THREADS) sh[i] = 0u;
    __syncthreads();
    for (int p = threadIdx.x; p < M; p += THREADS) {
        atomicAdd(&sh[flat3(pal[3 * p], pal[3 * p + 1], pal[3 * p + 2])], 1u);
    }
    __syncthreads();

    // hist sums are exactly npix and M; +1e-8 is a no-op in fp32 (matches ref).
    const float invS = 1.0f / ((float)npix + 1e-8f);
    const float invT = 1.0f / ((float)M + 1e-8f);

    float acc = 0.0f;
    for (int i = threadIdx.x; i < NPAIR; i += THREADS) {
        unsigned long long v = __ldcg(&g_hist64[i]);
        unsigned int lo = (unsigned int)v;
        unsigned int hi = (unsigned int)(v >> 32);
        acc += fabsf((float)lo * invS - (float)sh[2 * i]     * invT);
        acc += fabsf((float)hi * invS - (float)sh[2 * i + 1] * invT);
        g_hist64[i] = 0ull;                      // self-clean for next replay
    }

    for (int off = 16; off; off >>= 1) acc += __shfl_down_sync(0xffffffffu, acc, off);
    if ((threadIdx.x & 31) == 0) red[threadIdx.x >> 5] = acc;
    __syncthreads();
    if (threadIdx.x < 32) {
        float v = (threadIdx.x < THREADS / 32) ? red[threadIdx.x] : 0.0f;
        for (int off = 16; off; off >>= 1) v += __shfl_down_sync(0xffffffffu, v, off);
        if (threadIdx.x == 0) {
            out[0] = v * (1.0f / (float)NBINS);
            g_arrival = 0u;                      // self-clean for next replay
        }
    }
}

extern "C" void kernel_launch(void* const* d_in, const int* in_sizes, int n_in,
                              void* d_out, int out_size) {
    const float* src = (const float*)d_in[0];   // (N, 3) float32
    const float* pal = (const float*)d_in[1];   // (M, 3) float32
    int N = in_sizes[0] / 3;
    int M = in_sizes[1] / 3;
    int nquads = N / 4;

    fused_hist_loss_kernel<<<BLOCKS, THREADS>>>(
        (const float4*)src, src, pal, nquads, N, M, (float*)d_out);
}